// round 1
// baseline (speedup 1.0000x reference)
#include <cuda_runtime.h>
#include <math.h>

// Problem constants
constexpr int BATCH = 4;
constexpr int N_TOK = 2048;
constexpr int D_INP = 129;   // D_IN + 1 (time-lifted input)
constexpr int NH    = 8;
constexpr int DA    = 65;    // D_OUT + 1 ambient dim
constexpr int BHN   = BATCH * NH;   // 32
constexpr int VST   = 68;    // padded row stride for V / Mid

// Scratch (zero-init BSS; ~70 MB total, rewritten every call -> deterministic)
__device__ __align__(128) float g_Q  [BHN * DA * N_TOK];   // [bh][c][n], c-major; pre-scaled by alpha*log2e, time slot (c=64) = -alpha*q0
__device__ __align__(128) float g_K  [BHN * DA * N_TOK];   // [bh][c][n], c-major; time slot (c=64) = +k0
__device__ __align__(128) float g_V  [BHN * N_TOK * VST];  // [bh][n][c], cols 0..63 spatial, 64 time
__device__ __align__(128) float g_Mid[BHN * N_TOK * VST];  // per-head Lorentz-normalized midpoints

__device__ __forceinline__ float fexp2(float x) {
    float r; asm("ex2.approx.ftz.f32 %0, %1;" : "=f"(r) : "f"(x)); return r;
}

// ---------------------------------------------------------------------------
// Projection: s = x @ W + b per head, lift, fold alpha/sign, write c-major Q/K
// grid (128 m-tiles, 8 heads, 3 tensors), 256 threads
// ---------------------------------------------------------------------------
__global__ __launch_bounds__(256) void proj_kernel(
    const float* __restrict__ x,
    const float* __restrict__ Wq, const float* __restrict__ Wk, const float* __restrict__ Wv,
    const float* __restrict__ bq, const float* __restrict__ bk, const float* __restrict__ bv,
    const float* __restrict__ scale)
{
    extern __shared__ float sm[];
    float* xs = sm;               // [64][129]
    float* Ws = sm + 64 * D_INP;  // [129][64]; reused as smT [65][65]

    const int tid = threadIdx.x;
    const int ty = tid >> 4, tx = tid & 15;
    const int m0 = blockIdx.x * 64;
    const int h  = blockIdx.y;
    const int z  = blockIdx.z;    // 0=Q 1=K 2=V
    const float* W  = (z == 0) ? Wq : (z == 1 ? Wk : Wv);
    const float* bi = (z == 0) ? bq : (z == 1 ? bk : bv);

    for (int idx = tid; idx < 64 * D_INP; idx += 256)
        xs[idx] = x[m0 * D_INP + idx];
    for (int idx = tid; idx < D_INP * 64; idx += 256)
        Ws[idx] = W[h * D_INP * 64 + idx];
    __syncthreads();

    float s[4][4] = {};
    #pragma unroll 4
    for (int k = 0; k < D_INP; k++) {
        float a0 = xs[(4 * ty + 0) * D_INP + k];
        float a1 = xs[(4 * ty + 1) * D_INP + k];
        float a2 = xs[(4 * ty + 2) * D_INP + k];
        float a3 = xs[(4 * ty + 3) * D_INP + k];
        float4 w = *(const float4*)&Ws[k * 64 + 4 * tx];
        s[0][0] = fmaf(a0, w.x, s[0][0]); s[0][1] = fmaf(a0, w.y, s[0][1]);
        s[0][2] = fmaf(a0, w.z, s[0][2]); s[0][3] = fmaf(a0, w.w, s[0][3]);
        s[1][0] = fmaf(a1, w.x, s[1][0]); s[1][1] = fmaf(a1, w.y, s[1][1]);
        s[1][2] = fmaf(a1, w.z, s[1][2]); s[1][3] = fmaf(a1, w.w, s[1][3]);
        s[2][0] = fmaf(a2, w.x, s[2][0]); s[2][1] = fmaf(a2, w.y, s[2][1]);
        s[2][2] = fmaf(a2, w.z, s[2][2]); s[2][3] = fmaf(a2, w.w, s[2][3]);
        s[3][0] = fmaf(a3, w.x, s[3][0]); s[3][1] = fmaf(a3, w.y, s[3][1]);
        s[3][2] = fmaf(a3, w.z, s[3][2]); s[3][3] = fmaf(a3, w.w, s[3][3]);
    }
    float4 b4 = *(const float4*)&bi[h * 64 + 4 * tx];
    #pragma unroll
    for (int i = 0; i < 4; i++) {
        s[i][0] += b4.x; s[i][1] += b4.y; s[i][2] += b4.z; s[i][3] += b4.w;
    }

    // lift: t = sqrt(1 + ||s_row||^2); row spread over the 16 tx lanes of the group
    float tvals[4];
    #pragma unroll
    for (int i = 0; i < 4; i++) {
        float ss = s[i][0]*s[i][0] + s[i][1]*s[i][1] + s[i][2]*s[i][2] + s[i][3]*s[i][3];
        #pragma unroll
        for (int o = 1; o < 16; o <<= 1) ss += __shfl_xor_sync(0xffffffffu, ss, o);
        tvals[i] = sqrtf(1.0f + ss);
    }

    const int bh = (m0 >> 11) * NH + h;
    const int n0 = m0 & (N_TOK - 1);

    if (z == 2) {
        // V: n-major padded layout, direct float4 stores
        #pragma unroll
        for (int i = 0; i < 4; i++) {
            int n = n0 + 4 * ty + i;
            size_t base = (size_t)(bh * N_TOK + n) * VST;
            *(float4*)&g_V[base + 4 * tx] = make_float4(s[i][0], s[i][1], s[i][2], s[i][3]);
            if (tx == 0) g_V[base + 64] = tvals[i];
        }
    } else {
        float fac = 1.0f, tfac = 1.0f;
        if (z == 0) {
            float sc = *scale;
            fac  = 2.0f * 1.4426950408889634f / (sc + 1e-7f);  // alpha * log2(e)
            tfac = -fac;                                        // Lorentz sign on time
        }
        __syncthreads();                 // done with Ws as weights
        float* smT = Ws;                 // [65][65] transpose staging
        #pragma unroll
        for (int i = 0; i < 4; i++) {
            #pragma unroll
            for (int j = 0; j < 4; j++)
                smT[(4 * tx + j) * 65 + 4 * ty + i] = fac * s[i][j];
            if (tx == 0) smT[64 * 65 + 4 * ty + i] = tfac * tvals[i];
        }
        __syncthreads();
        float* g = (z == 0) ? g_Q : g_K;
        for (int idx = tid; idx < 65 * 64; idx += 256) {
            int c = idx >> 6, r = idx & 63;
            g[(size_t)(bh * DA + c) * N_TOK + n0 + r] = smT[c * 65 + r];
        }
    }
}

// ---------------------------------------------------------------------------
// Flash attention, fp32, 128x128 tiles, online softmax, fused per-head
// Lorentz midpoint normalization. grid (16 q-tiles, 32 bh), 256 threads.
// ---------------------------------------------------------------------------
__global__ __launch_bounds__(256, 1) void attn_kernel()
{
    extern __shared__ float sm[];
    float* qt = sm;                       // [65][128]  component-major Q tile
    float* kt = qt + 65 * 128;            // [65][128]
    float* vs = kt + 65 * 128;            // [128][68]
    float* ps = vs + 128 * VST;           // [128][132] probabilities

    const int tid = threadIdx.x;
    const int ty = tid >> 4, tx = tid & 15;
    const int bh = blockIdx.y;
    const int q0 = blockIdx.x * 128;

    for (int idx = tid; idx < 65 * 128; idx += 256) {
        int c = idx >> 7, r = idx & 127;
        qt[idx] = g_Q[(size_t)(bh * DA + c) * N_TOK + q0 + r];
    }

    float m[8], l[8], acc[8][5];
    #pragma unroll
    for (int i = 0; i < 8; i++) {
        m[i] = -1e30f; l[i] = 0.0f;
        #pragma unroll
        for (int j = 0; j < 5; j++) acc[i][j] = 0.0f;
    }
    __syncthreads();

    for (int k0 = 0; k0 < N_TOK; k0 += 128) {
        for (int idx = tid; idx < 65 * 128; idx += 256) {
            int c = idx >> 7, r = idx & 127;
            kt[idx] = g_K[(size_t)(bh * DA + c) * N_TOK + k0 + r];
        }
        {
            const float4* gv = (const float4*)&g_V[(size_t)(bh * N_TOK + k0) * VST];
            float4* v4 = (float4*)vs;
            for (int idx = tid; idx < 128 * (VST / 4); idx += 256) v4[idx] = gv[idx];
        }
        __syncthreads();

        // ---- S = Qe . Ke (scores already in log2 domain, alpha folded) ----
        float s[8][8];
        #pragma unroll
        for (int i = 0; i < 8; i++)
            #pragma unroll
            for (int j = 0; j < 8; j++) s[i][j] = 0.0f;

        #pragma unroll 2
        for (int d = 0; d < DA; d++) {
            const float* qr = qt + d * 128;
            const float* kr = kt + d * 128;
            float4 qa = *(const float4*)(qr + 4 * ty);
            float4 qb = *(const float4*)(qr + 64 + 4 * ty);
            float4 ka = *(const float4*)(kr + 4 * tx);
            float4 kb = *(const float4*)(kr + 64 + 4 * tx);
            float qv[8] = {qa.x, qa.y, qa.z, qa.w, qb.x, qb.y, qb.z, qb.w};
            float kv[8] = {ka.x, ka.y, ka.z, ka.w, kb.x, kb.y, kb.z, kb.w};
            #pragma unroll
            for (int i = 0; i < 8; i++)
                #pragma unroll
                for (int j = 0; j < 8; j++)
                    s[i][j] = fmaf(qv[i], kv[j], s[i][j]);
        }

        // ---- online softmax (base-2) ----
        #pragma unroll
        for (int i = 0; i < 8; i++) {
            float mx = s[i][0];
            #pragma unroll
            for (int j = 1; j < 8; j++) mx = fmaxf(mx, s[i][j]);
            #pragma unroll
            for (int o = 1; o < 16; o <<= 1) mx = fmaxf(mx, __shfl_xor_sync(0xffffffffu, mx, o));
            float mn = fmaxf(m[i], mx);
            float corr = fexp2(m[i] - mn);
            m[i] = mn;
            float rs = 0.0f;
            #pragma unroll
            for (int j = 0; j < 8; j++) { float p = fexp2(s[i][j] - mn); s[i][j] = p; rs += p; }
            #pragma unroll
            for (int o = 1; o < 16; o <<= 1) rs += __shfl_xor_sync(0xffffffffu, rs, o);
            l[i] = l[i] * corr + rs;
            #pragma unroll
            for (int j = 0; j < 5; j++) acc[i][j] *= corr;
        }

        // ---- stage P to smem ----
        #pragma unroll
        for (int i = 0; i < 8; i++) {
            int r = (i < 4) ? (4 * ty + i) : (60 + 4 * ty + i);
            *(float4*)&ps[r * 132 + 4 * tx]      = make_float4(s[i][0], s[i][1], s[i][2], s[i][3]);
            *(float4*)&ps[r * 132 + 64 + 4 * tx] = make_float4(s[i][4], s[i][5], s[i][6], s[i][7]);
        }
        __syncthreads();

        // ---- O += P @ V (65 cols; col 64 = time, replicated across lanes) ----
        #pragma unroll 1
        for (int kk = 0; kk < 128; kk += 4) {
            float4 p4[8];
            #pragma unroll
            for (int i = 0; i < 8; i++) {
                int r = (i < 4) ? (4 * ty + i) : (60 + 4 * ty + i);
                p4[i] = *(const float4*)&ps[r * 132 + kk];
            }
            #pragma unroll
            for (int u = 0; u < 4; u++) {
                float4 v4 = *(const float4*)&vs[(kk + u) * VST + 4 * tx];
                float  vt = vs[(kk + u) * VST + 64];
                #pragma unroll
                for (int i = 0; i < 8; i++) {
                    float p = (u == 0) ? p4[i].x : (u == 1) ? p4[i].y : (u == 2) ? p4[i].z : p4[i].w;
                    acc[i][0] = fmaf(p, v4.x, acc[i][0]);
                    acc[i][1] = fmaf(p, v4.y, acc[i][1]);
                    acc[i][2] = fmaf(p, v4.z, acc[i][2]);
                    acc[i][3] = fmaf(p, v4.w, acc[i][3]);
                    acc[i][4] = fmaf(p, vt,   acc[i][4]);
                }
            }
        }
        __syncthreads();
    }

    // ---- epilogue: mu = acc/l; per-head Lorentz normalize; store Mid ----
    #pragma unroll
    for (int i = 0; i < 8; i++) {
        float inv = 1.0f / l[i];
        float mu0 = acc[i][0] * inv, mu1 = acc[i][1] * inv;
        float mu2 = acc[i][2] * inv, mu3 = acc[i][3] * inv;
        float mut = acc[i][4] * inv;                  // identical across the 16 lanes
        float part = -(mu0 * mu0 + mu1 * mu1 + mu2 * mu2 + mu3 * mu3);
        if (tx == 0) part += mut * mut;               // + t^2 once
        #pragma unroll
        for (int o = 1; o < 16; o <<= 1) part += __shfl_xor_sync(0xffffffffu, part, o);
        float rn = rsqrtf(fmaxf(part, 1e-7f));        // 1/sqrt(clip(t^2 - ||s||^2, EPS))
        int r = (i < 4) ? (4 * ty + i) : (60 + 4 * ty + i);
        size_t base = (size_t)(bh * N_TOK + q0 + r) * VST;
        *(float4*)&g_Mid[base + 4 * tx] = make_float4(mu0 * rn, mu1 * rn, mu2 * rn, mu3 * rn);
        if (tx == 0) g_Mid[base + 64] = mut * rn;
    }
}

// ---------------------------------------------------------------------------
// Finalize: mean over heads, Lorentz normalize, re-lift. One warp per (b,n).
// ---------------------------------------------------------------------------
__global__ __launch_bounds__(256) void fin_kernel(float* __restrict__ out)
{
    int warp = threadIdx.x >> 5, lane = threadIdx.x & 31;
    int row = blockIdx.x * 8 + warp;            // 0..8191
    int b = row >> 11, n = row & (N_TOK - 1);

    float sa = 0.0f, sb = 0.0f, st = 0.0f;
    #pragma unroll
    for (int h = 0; h < NH; h++) {
        const float* p = &g_Mid[(size_t)((b * NH + h) * N_TOK + n) * VST];
        sa += p[lane];
        sb += p[32 + lane];
        if (lane == 0) st += p[64];
    }
    sa *= 0.125f; sb *= 0.125f; st *= 0.125f;   // mean over heads

    float part = -(sa * sa + sb * sb);
    if (lane == 0) part += st * st;
    #pragma unroll
    for (int o = 1; o < 32; o <<= 1) part += __shfl_xor_sync(0xffffffffu, part, o);
    float rn = rsqrtf(fmaxf(part, 1e-7f));

    float oa = sa * rn, ob = sb * rn;           // normalized spatial components
    float sp = oa * oa + ob * ob;
    #pragma unroll
    for (int o = 1; o < 32; o <<= 1) sp += __shfl_xor_sync(0xffffffffu, sp, o);

    float* op = out + (size_t)row * DA;
    op[1 + lane]  = oa;                          // spatial 0..31
    op[33 + lane] = ob;                          // spatial 32..63
    if (lane == 0) op[0] = sqrtf(1.0f + sp);     // re-lifted time
}

// ---------------------------------------------------------------------------
extern "C" void kernel_launch(void* const* d_in, const int* in_sizes, int n_in,
                              void* d_out, int out_size)
{
    const float* x     = (const float*)d_in[0];
    const float* Wq    = (const float*)d_in[1];
    const float* Wk    = (const float*)d_in[2];
    const float* Wv    = (const float*)d_in[3];
    const float* bq    = (const float*)d_in[4];
    const float* bk    = (const float*)d_in[5];
    const float* bv    = (const float*)d_in[6];
    const float* scale = (const float*)d_in[7];
    (void)in_sizes; (void)n_in;

    const int smem_proj = (64 * D_INP + D_INP * 64) * 4;                          // 66 KB
    const int smem_attn = (65 * 128 * 2 + 128 * VST + 128 * 132) * 4;             // 165 KB
    cudaFuncSetAttribute(proj_kernel, cudaFuncAttributeMaxDynamicSharedMemorySize, smem_proj);
    cudaFuncSetAttribute(attn_kernel, cudaFuncAttributeMaxDynamicSharedMemorySize, smem_attn);

    proj_kernel<<<dim3(BATCH * N_TOK / 64, NH, 3), 256, smem_proj>>>(x, Wq, Wk, Wv, bq, bk, bv, scale);
    attn_kernel<<<dim3(N_TOK / 128, BHN), 256, smem_attn>>>();
    fin_kernel<<<(BATCH * N_TOK) / 8, 256>>>((float*)d_out);
}

// round 2
// speedup vs baseline: 1.0028x; 1.0028x over previous
#include <cuda_runtime.h>
#include <math.h>

// Problem constants
constexpr int BATCH = 4;
constexpr int N_TOK = 2048;
constexpr int D_INP = 129;   // D_IN + 1 (time-lifted input)
constexpr int NH    = 8;
constexpr int DA    = 65;    // D_OUT + 1 ambient dim
constexpr int BHN   = BATCH * NH;   // 32
constexpr int VST   = 68;    // padded row stride for V / Mid

// Scratch (zero-init BSS; ~70 MB total, rewritten every call -> deterministic)
__device__ __align__(128) float g_Q  [BHN * DA * N_TOK];   // [bh][c][n], c-major; pre-scaled by alpha*log2e, time slot (c=64) = -alpha*q0
__device__ __align__(128) float g_K  [BHN * DA * N_TOK];   // [bh][c][n], c-major; time slot (c=64) = +k0
__device__ __align__(128) float g_V  [BHN * N_TOK * VST];  // [bh][n][c], cols 0..63 spatial, 64 time
__device__ __align__(128) float g_Mid[BHN * N_TOK * VST];  // per-head Lorentz-normalized midpoints

__device__ __forceinline__ float fexp2(float x) {
    float r; asm("ex2.approx.ftz.f32 %0, %1;" : "=f"(r) : "f"(x)); return r;
}

// ---------------------------------------------------------------------------
// Projection: s = x @ W + b per head, lift, fold alpha/sign, write c-major Q/K
// grid (128 m-tiles, 8 heads, 3 tensors), 256 threads
// ---------------------------------------------------------------------------
__global__ __launch_bounds__(256) void proj_kernel(
    const float* __restrict__ x,
    const float* __restrict__ Wq, const float* __restrict__ Wk, const float* __restrict__ Wv,
    const float* __restrict__ bq, const float* __restrict__ bk, const float* __restrict__ bv,
    const float* __restrict__ scale)
{
    extern __shared__ float sm[];
    float* xs = sm;               // [64][129]
    float* Ws = sm + 64 * D_INP;  // [129][64]; reused as smT [65][65]

    const int tid = threadIdx.x;
    const int ty = tid >> 4, tx = tid & 15;
    const int m0 = blockIdx.x * 64;
    const int h  = blockIdx.y;
    const int z  = blockIdx.z;    // 0=Q 1=K 2=V
    const float* W  = (z == 0) ? Wq : (z == 1 ? Wk : Wv);
    const float* bi = (z == 0) ? bq : (z == 1 ? bk : bv);

    for (int idx = tid; idx < 64 * D_INP; idx += 256)
        xs[idx] = x[m0 * D_INP + idx];
    for (int idx = tid; idx < D_INP * 64; idx += 256)
        Ws[idx] = W[h * D_INP * 64 + idx];
    __syncthreads();

    float s[4][4] = {};
    #pragma unroll 4
    for (int k = 0; k < D_INP; k++) {
        float a0 = xs[(4 * ty + 0) * D_INP + k];
        float a1 = xs[(4 * ty + 1) * D_INP + k];
        float a2 = xs[(4 * ty + 2) * D_INP + k];
        float a3 = xs[(4 * ty + 3) * D_INP + k];
        float4 w = *(const float4*)&Ws[k * 64 + 4 * tx];
        s[0][0] = fmaf(a0, w.x, s[0][0]); s[0][1] = fmaf(a0, w.y, s[0][1]);
        s[0][2] = fmaf(a0, w.z, s[0][2]); s[0][3] = fmaf(a0, w.w, s[0][3]);
        s[1][0] = fmaf(a1, w.x, s[1][0]); s[1][1] = fmaf(a1, w.y, s[1][1]);
        s[1][2] = fmaf(a1, w.z, s[1][2]); s[1][3] = fmaf(a1, w.w, s[1][3]);
        s[2][0] = fmaf(a2, w.x, s[2][0]); s[2][1] = fmaf(a2, w.y, s[2][1]);
        s[2][2] = fmaf(a2, w.z, s[2][2]); s[2][3] = fmaf(a2, w.w, s[2][3]);
        s[3][0] = fmaf(a3, w.x, s[3][0]); s[3][1] = fmaf(a3, w.y, s[3][1]);
        s[3][2] = fmaf(a3, w.z, s[3][2]); s[3][3] = fmaf(a3, w.w, s[3][3]);
    }
    float4 b4 = *(const float4*)&bi[h * 64 + 4 * tx];
    #pragma unroll
    for (int i = 0; i < 4; i++) {
        s[i][0] += b4.x; s[i][1] += b4.y; s[i][2] += b4.z; s[i][3] += b4.w;
    }

    // lift: t = sqrt(1 + ||s_row||^2); row spread over the 16 tx lanes of the group
    float tvals[4];
    #pragma unroll
    for (int i = 0; i < 4; i++) {
        float ss = s[i][0]*s[i][0] + s[i][1]*s[i][1] + s[i][2]*s[i][2] + s[i][3]*s[i][3];
        #pragma unroll
        for (int o = 1; o < 16; o <<= 1) ss += __shfl_xor_sync(0xffffffffu, ss, o);
        tvals[i] = sqrtf(1.0f + ss);
    }

    const int bh = (m0 >> 11) * NH + h;
    const int n0 = m0 & (N_TOK - 1);

    if (z == 2) {
        // V: n-major padded layout, direct float4 stores
        #pragma unroll
        for (int i = 0; i < 4; i++) {
            int n = n0 + 4 * ty + i;
            size_t base = (size_t)(bh * N_TOK + n) * VST;
            *(float4*)&g_V[base + 4 * tx] = make_float4(s[i][0], s[i][1], s[i][2], s[i][3]);
            if (tx == 0) g_V[base + 64] = tvals[i];
        }
    } else {
        float fac = 1.0f, tfac = 1.0f;
        if (z == 0) {
            float sc = *scale;
            fac  = 2.0f * 1.4426950408889634f / (sc + 1e-7f);  // alpha * log2(e)
            tfac = -fac;                                        // Lorentz sign on time
        }
        __syncthreads();                 // done with Ws as weights
        float* smT = Ws;                 // [65][65] transpose staging
        #pragma unroll
        for (int i = 0; i < 4; i++) {
            #pragma unroll
            for (int j = 0; j < 4; j++)
                smT[(4 * tx + j) * 65 + 4 * ty + i] = fac * s[i][j];
            if (tx == 0) smT[64 * 65 + 4 * ty + i] = tfac * tvals[i];
        }
        __syncthreads();
        float* g = (z == 0) ? g_Q : g_K;
        for (int idx = tid; idx < 65 * 64; idx += 256) {
            int c = idx >> 6, r = idx & 63;
            g[(size_t)(bh * DA + c) * N_TOK + n0 + r] = smT[c * 65 + r];
        }
    }
}

// ---------------------------------------------------------------------------
// Flash attention, fp32, 128x128 tiles, online softmax, fused per-head
// Lorentz midpoint normalization. grid (16 q-tiles, 32 bh), 256 threads.
// ---------------------------------------------------------------------------
__global__ __launch_bounds__(256, 1) void attn_kernel()
{
    extern __shared__ float sm[];
    float* qt = sm;                       // [65][128]  component-major Q tile
    float* kt = qt + 65 * 128;            // [65][128]
    float* vs = kt + 65 * 128;            // [128][68]
    float* ps = vs + 128 * VST;           // [128][132] probabilities

    const int tid = threadIdx.x;
    const int ty = tid >> 4, tx = tid & 15;
    const int bh = blockIdx.y;
    const int q0 = blockIdx.x * 128;

    for (int idx = tid; idx < 65 * 128; idx += 256) {
        int c = idx >> 7, r = idx & 127;
        qt[idx] = g_Q[(size_t)(bh * DA + c) * N_TOK + q0 + r];
    }

    float m[8], l[8], acc[8][5];
    #pragma unroll
    for (int i = 0; i < 8; i++) {
        m[i] = -1e30f; l[i] = 0.0f;
        #pragma unroll
        for (int j = 0; j < 5; j++) acc[i][j] = 0.0f;
    }
    __syncthreads();

    for (int k0 = 0; k0 < N_TOK; k0 += 128) {
        for (int idx = tid; idx < 65 * 128; idx += 256) {
            int c = idx >> 7, r = idx & 127;
            kt[idx] = g_K[(size_t)(bh * DA + c) * N_TOK + k0 + r];
        }
        {
            const float4* gv = (const float4*)&g_V[(size_t)(bh * N_TOK + k0) * VST];
            float4* v4 = (float4*)vs;
            for (int idx = tid; idx < 128 * (VST / 4); idx += 256) v4[idx] = gv[idx];
        }
        __syncthreads();

        // ---- S = Qe . Ke (scores already in log2 domain, alpha folded) ----
        float s[8][8];
        #pragma unroll
        for (int i = 0; i < 8; i++)
            #pragma unroll
            for (int j = 0; j < 8; j++) s[i][j] = 0.0f;

        #pragma unroll 2
        for (int d = 0; d < DA; d++) {
            const float* qr = qt + d * 128;
            const float* kr = kt + d * 128;
            float4 qa = *(const float4*)(qr + 4 * ty);
            float4 qb = *(const float4*)(qr + 64 + 4 * ty);
            float4 ka = *(const float4*)(kr + 4 * tx);
            float4 kb = *(const float4*)(kr + 64 + 4 * tx);
            float qv[8] = {qa.x, qa.y, qa.z, qa.w, qb.x, qb.y, qb.z, qb.w};
            float kv[8] = {ka.x, ka.y, ka.z, ka.w, kb.x, kb.y, kb.z, kb.w};
            #pragma unroll
            for (int i = 0; i < 8; i++)
                #pragma unroll
                for (int j = 0; j < 8; j++)
                    s[i][j] = fmaf(qv[i], kv[j], s[i][j]);
        }

        // ---- online softmax (base-2) ----
        #pragma unroll
        for (int i = 0; i < 8; i++) {
            float mx = s[i][0];
            #pragma unroll
            for (int j = 1; j < 8; j++) mx = fmaxf(mx, s[i][j]);
            #pragma unroll
            for (int o = 1; o < 16; o <<= 1) mx = fmaxf(mx, __shfl_xor_sync(0xffffffffu, mx, o));
            float mn = fmaxf(m[i], mx);
            float corr = fexp2(m[i] - mn);
            m[i] = mn;
            float rs = 0.0f;
            #pragma unroll
            for (int j = 0; j < 8; j++) { float p = fexp2(s[i][j] - mn); s[i][j] = p; rs += p; }
            #pragma unroll
            for (int o = 1; o < 16; o <<= 1) rs += __shfl_xor_sync(0xffffffffu, rs, o);
            l[i] = l[i] * corr + rs;
            #pragma unroll
            for (int j = 0; j < 5; j++) acc[i][j] *= corr;
        }

        // ---- stage P to smem ----
        #pragma unroll
        for (int i = 0; i < 8; i++) {
            int r = (i < 4) ? (4 * ty + i) : (60 + 4 * ty + i);
            *(float4*)&ps[r * 132 + 4 * tx]      = make_float4(s[i][0], s[i][1], s[i][2], s[i][3]);
            *(float4*)&ps[r * 132 + 64 + 4 * tx] = make_float4(s[i][4], s[i][5], s[i][6], s[i][7]);
        }
        __syncthreads();

        // ---- O += P @ V (65 cols; col 64 = time, replicated across lanes) ----
        #pragma unroll 1
        for (int kk = 0; kk < 128; kk += 4) {
            float4 p4[8];
            #pragma unroll
            for (int i = 0; i < 8; i++) {
                int r = (i < 4) ? (4 * ty + i) : (60 + 4 * ty + i);
                p4[i] = *(const float4*)&ps[r * 132 + kk];
            }
            #pragma unroll
            for (int u = 0; u < 4; u++) {
                float4 v4 = *(const float4*)&vs[(kk + u) * VST + 4 * tx];
                float  vt = vs[(kk + u) * VST + 64];
                #pragma unroll
                for (int i = 0; i < 8; i++) {
                    float p = (u == 0) ? p4[i].x : (u == 1) ? p4[i].y : (u == 2) ? p4[i].z : p4[i].w;
                    acc[i][0] = fmaf(p, v4.x, acc[i][0]);
                    acc[i][1] = fmaf(p, v4.y, acc[i][1]);
                    acc[i][2] = fmaf(p, v4.z, acc[i][2]);
                    acc[i][3] = fmaf(p, v4.w, acc[i][3]);
                    acc[i][4] = fmaf(p, vt,   acc[i][4]);
                }
            }
        }
        __syncthreads();
    }

    // ---- epilogue: mu = acc/l; per-head Lorentz normalize; store Mid ----
    #pragma unroll
    for (int i = 0; i < 8; i++) {
        float inv = 1.0f / l[i];
        float mu0 = acc[i][0] * inv, mu1 = acc[i][1] * inv;
        float mu2 = acc[i][2] * inv, mu3 = acc[i][3] * inv;
        float mut = acc[i][4] * inv;                  // identical across the 16 lanes
        float part = -(mu0 * mu0 + mu1 * mu1 + mu2 * mu2 + mu3 * mu3);
        if (tx == 0) part += mut * mut;               // + t^2 once
        #pragma unroll
        for (int o = 1; o < 16; o <<= 1) part += __shfl_xor_sync(0xffffffffu, part, o);
        float rn = rsqrtf(fmaxf(part, 1e-7f));        // 1/sqrt(clip(t^2 - ||s||^2, EPS))
        int r = (i < 4) ? (4 * ty + i) : (60 + 4 * ty + i);
        size_t base = (size_t)(bh * N_TOK + q0 + r) * VST;
        *(float4*)&g_Mid[base + 4 * tx] = make_float4(mu0 * rn, mu1 * rn, mu2 * rn, mu3 * rn);
        if (tx == 0) g_Mid[base + 64] = mut * rn;
    }
}

// ---------------------------------------------------------------------------
// Finalize: mean over heads, Lorentz normalize, re-lift. One warp per (b,n).
// ---------------------------------------------------------------------------
__global__ __launch_bounds__(256) void fin_kernel(float* __restrict__ out)
{
    int warp = threadIdx.x >> 5, lane = threadIdx.x & 31;
    int row = blockIdx.x * 8 + warp;            // 0..8191
    int b = row >> 11, n = row & (N_TOK - 1);

    float sa = 0.0f, sb = 0.0f, st = 0.0f;
    #pragma unroll
    for (int h = 0; h < NH; h++) {
        const float* p = &g_Mid[(size_t)((b * NH + h) * N_TOK + n) * VST];
        sa += p[lane];
        sb += p[32 + lane];
        if (lane == 0) st += p[64];
    }
    sa *= 0.125f; sb *= 0.125f; st *= 0.125f;   // mean over heads

    float part = -(sa * sa + sb * sb);
    if (lane == 0) part += st * st;
    #pragma unroll
    for (int o = 1; o < 32; o <<= 1) part += __shfl_xor_sync(0xffffffffu, part, o);
    float rn = rsqrtf(fmaxf(part, 1e-7f));

    float oa = sa * rn, ob = sb * rn;           // normalized spatial components
    float sp = oa * oa + ob * ob;
    #pragma unroll
    for (int o = 1; o < 32; o <<= 1) sp += __shfl_xor_sync(0xffffffffu, sp, o);

    float* op = out + (size_t)row * DA;
    op[1 + lane]  = oa;                          // spatial 0..31
    op[33 + lane] = ob;                          // spatial 32..63
    if (lane == 0) op[0] = sqrtf(1.0f + sp);     // re-lifted time
}

// ---------------------------------------------------------------------------
extern "C" void kernel_launch(void* const* d_in, const int* in_sizes, int n_in,
                              void* d_out, int out_size)
{
    const float* x     = (const float*)d_in[0];
    const float* Wq    = (const float*)d_in[1];
    const float* Wk    = (const float*)d_in[2];
    const float* Wv    = (const float*)d_in[3];
    const float* bq    = (const float*)d_in[4];
    const float* bk    = (const float*)d_in[5];
    const float* bv    = (const float*)d_in[6];
    const float* scale = (const float*)d_in[7];
    (void)in_sizes; (void)n_in;

    const int smem_proj = (64 * D_INP + D_INP * 64) * 4;                          // 66 KB
    const int smem_attn = (65 * 128 * 2 + 128 * VST + 128 * 132) * 4;             // 165 KB
    cudaFuncSetAttribute(proj_kernel, cudaFuncAttributeMaxDynamicSharedMemorySize, smem_proj);
    cudaFuncSetAttribute(attn_kernel, cudaFuncAttributeMaxDynamicSharedMemorySize, smem_attn);

    proj_kernel<<<dim3(BATCH * N_TOK / 64, NH, 3), 256, smem_proj>>>(x, Wq, Wk, Wv, bq, bk, bv, scale);
    attn_kernel<<<dim3(N_TOK / 128, BHN), 256, smem_attn>>>();
    fin_kernel<<<(BATCH * N_TOK) / 8, 256>>>((float*)d_out);
}

// round 4
// speedup vs baseline: 5.1972x; 5.1825x over previous
#include <cuda_runtime.h>
#include <cuda_fp16.h>
#include <math.h>
#include <stdint.h>

constexpr int BATCH = 4, N_TOK = 2048, D_INP = 129, NH = 8, BHN = 32, VST = 68;
constexpr int DF = 80;      // padded feature dim (64 spatial + 3 extras + 13 zero)

// Scratch (BSS zero-init; pad columns 67-79 are never written -> stay zero)
__device__ __align__(128) __half g_Qh[BHN * N_TOK * DF];
__device__ __align__(128) __half g_Kh[BHN * N_TOK * DF];
__device__ __align__(128) __half g_Vh[BHN * 64 * N_TOK];   // d-major: [bh][d][n]
__device__ __align__(128) float  g_Vt [BHN * N_TOK];
__device__ __align__(128) float  g_Mid[BHN * N_TOK * VST];

__device__ __forceinline__ float fexp2(float x) {
    float r; asm("ex2.approx.ftz.f32 %0, %1;" : "=f"(r) : "f"(x)); return r;
}
__device__ __forceinline__ uint32_t smem_u32(const void* p) {
    uint32_t a;
    asm("{ .reg .u64 t; cvta.to.shared.u64 t, %1; cvt.u32.u64 %0, t; }" : "=r"(a) : "l"(p));
    return a;
}
__device__ __forceinline__ void cpa16(uint32_t d, const void* s) {
    asm volatile("cp.async.cg.shared.global [%0], [%1], 16;" :: "r"(d), "l"(s));
}
#define CP_COMMIT() asm volatile("cp.async.commit_group;")
__device__ __forceinline__ void mma16816(float* c, const uint32_t* a, uint32_t b0, uint32_t b1) {
    asm volatile("mma.sync.aligned.m16n8k16.row.col.f32.f16.f16.f32 "
                 "{%0,%1,%2,%3},{%4,%5,%6,%7},{%8,%9},{%0,%1,%2,%3};"
                 : "+f"(c[0]), "+f"(c[1]), "+f"(c[2]), "+f"(c[3])
                 : "r"(a[0]), "r"(a[1]), "r"(a[2]), "r"(a[3]), "r"(b0), "r"(b1));
}
__device__ __forceinline__ uint32_t packh2(float lo, float hi) {
    __half2 h = __floats2half2_rn(lo, hi);
    return *(uint32_t*)&h;
}

// ---------------------------------------------------------------------------
// Projection: s = x @ W + b per head, lift, fold alpha, write fp16 operands.
// grid (128 m-tiles, 8 heads, 3 tensors), 256 threads.
// ---------------------------------------------------------------------------
__global__ __launch_bounds__(256) void proj_kernel(
    const float* __restrict__ x,
    const float* __restrict__ Wq, const float* __restrict__ Wk, const float* __restrict__ Wv,
    const float* __restrict__ bq, const float* __restrict__ bk, const float* __restrict__ bv,
    const float* __restrict__ scale)
{
    extern __shared__ float sm[];
    float* xs = sm;               // [64][129]
    float* Ws = sm + 64 * D_INP;  // [129][64]
    const int tid = threadIdx.x, ty = tid >> 4, tx = tid & 15;
    const int m0 = blockIdx.x * 64, h = blockIdx.y, z = blockIdx.z;
    const float* W  = (z == 0) ? Wq : (z == 1 ? Wk : Wv);
    const float* bi = (z == 0) ? bq : (z == 1 ? bk : bv);

    for (int i = tid; i < 64 * D_INP; i += 256) xs[i] = x[m0 * D_INP + i];
    for (int i = tid; i < D_INP * 64; i += 256) Ws[i] = W[h * D_INP * 64 + i];
    __syncthreads();

    float s[4][4] = {};
    #pragma unroll 4
    for (int k = 0; k < D_INP; k++) {
        float a[4];
        #pragma unroll
        for (int i = 0; i < 4; i++) a[i] = xs[(4 * ty + i) * D_INP + k];
        float4 w = *(const float4*)&Ws[k * 64 + 4 * tx];
        #pragma unroll
        for (int i = 0; i < 4; i++) {
            s[i][0] = fmaf(a[i], w.x, s[i][0]); s[i][1] = fmaf(a[i], w.y, s[i][1]);
            s[i][2] = fmaf(a[i], w.z, s[i][2]); s[i][3] = fmaf(a[i], w.w, s[i][3]);
        }
    }
    float4 b4 = *(const float4*)&bi[h * 64 + 4 * tx];
    #pragma unroll
    for (int i = 0; i < 4; i++) { s[i][0] += b4.x; s[i][1] += b4.y; s[i][2] += b4.z; s[i][3] += b4.w; }

    float tvals[4], ap[4];
    #pragma unroll
    for (int i = 0; i < 4; i++) {
        float ss = s[i][0]*s[i][0] + s[i][1]*s[i][1] + s[i][2]*s[i][2] + s[i][3]*s[i][3];
        #pragma unroll
        for (int o = 1; o < 16; o <<= 1) ss += __shfl_xor_sync(0xffffffffu, ss, o);
        tvals[i] = sqrtf(1.0f + ss);
        ap[i] = ss / (1.0f + tvals[i]);     // t - 1, numerically stable
    }

    const int bh = (m0 >> 11) * NH + h;
    const int n0 = m0 & (N_TOK - 1);

    if (z == 2) {
        // V d-major fp16 + fp32 time
        #pragma unroll
        for (int i = 0; i < 4; i++) {
            int n = n0 + 4 * ty + i;
            #pragma unroll
            for (int j = 0; j < 4; j++)
                g_Vh[((size_t)(bh * 64 + 4 * tx + j)) * N_TOK + n] = __float2half_rn(s[i][j]);
            if (tx == 0) g_Vt[bh * N_TOK + n] = tvals[i];
        }
    } else {
        float fac = 1.0f;
        if (z == 0) { float sc = *scale; fac = 2.0f * 1.4426950408889634f / (sc + 1e-7f); }
        __half* g = (z == 0) ? g_Qh : g_Kh;
        #pragma unroll
        for (int i = 0; i < 4; i++) {
            int n = n0 + 4 * ty + i;
            size_t rb = (size_t)(bh * N_TOK + n) * DF;
            *(__half2*)&g[rb + 4 * tx]     = __floats2half2_rn(fac * s[i][0], fac * s[i][1]);
            *(__half2*)&g[rb + 4 * tx + 2] = __floats2half2_rn(fac * s[i][2], fac * s[i][3]);
            if (tx == 0) {
                float e64, e65, e66;
                if (z == 0) { e64 = -fac * ap[i]; e65 = -fac;  e66 = -fac * ap[i]; }
                else        { e64 = 1.0f;         e65 = ap[i]; e66 = ap[i]; }
                *(__half2*)&g[rb + 64] = __floats2half2_rn(e64, e65);
                *(__half2*)&g[rb + 66] = __floats2half2_rn(e66, 0.0f);
            }
        }
    }
}

// ---------------------------------------------------------------------------
// FA2-style fp16 flash attention, fixed-max-0 softmax.
// grid (16 q-tiles, 32 bh), 128 threads (4 warps x 32 q-rows).
// smem (halves): Qs[128*88] | Ks[2][64*88] | Vs[2][64*72] | vts[2][64] (f32)
// ---------------------------------------------------------------------------
constexpr int QSTR = 88, VSTR = 72;
constexpr int SMEM_ATTN = 64000;

__global__ __launch_bounds__(128, 1) void attn_kernel()
{
    extern __shared__ __align__(16) __half smh[];
    __half* Qs = smh;                       // 11264 halves
    __half* Ks = smh + 11264;               // 2 x 5632
    __half* Vs = smh + 22528;               // 2 x 4608
    float*  vts = (float*)(smh + 31744);    // 2 x 64 floats

    const uint32_t smb = smem_u32(smh);
    const int tid = threadIdx.x;
    const int w = tid >> 5, lane = tid & 31;
    const int qr = lane >> 2, qc2 = (lane & 3) * 2;
    const int bh = blockIdx.y, qt = blockIdx.x;

    const __half* gQ = g_Qh + (size_t)bh * N_TOK * DF + (size_t)qt * 128 * DF;
    const __half* gK = g_Kh + (size_t)bh * N_TOK * DF;
    const __half* gV = g_Vh + (size_t)bh * 64 * N_TOK;
    const float*  gvt = g_Vt + bh * N_TOK;

    const uint32_t ksb[2] = { smb + 11264u * 2, smb + 16896u * 2 };
    const uint32_t vsb[2] = { smb + 22528u * 2, smb + 27136u * 2 };
    const uint32_t vtb[2] = { smb + 31744u * 2, smb + 31744u * 2 + 256 };

    // prologue: Q + chunk0 in group0, chunk1 in group1
    for (int i = tid; i < 1280; i += 128) {
        int r = i / 10, sg = i % 10;
        cpa16(smb + (r * QSTR + sg * 8) * 2, gQ + r * DF + sg * 8);
    }
    #pragma unroll 1
    for (int c = 0; c < 2; c++) {
        int k0 = c * 64;
        for (int i = tid; i < 640; i += 128) {
            int key = i / 10, sg = i % 10;
            cpa16(ksb[c] + (key * QSTR + sg * 8) * 2, gK + (k0 + key) * DF + sg * 8);
        }
        for (int i = tid; i < 512; i += 128) {
            int d = i >> 3, sg = i & 7;
            cpa16(vsb[c] + (d * VSTR + sg * 8) * 2, gV + (size_t)d * N_TOK + k0 + sg * 8);
        }
        if (tid < 16) cpa16(vtb[c] + tid * 16, gvt + k0 + tid * 4);
        CP_COMMIT();
    }

    uint32_t qf[2][5][4];
    float O[2][8][4];
    float lp[2][2] = {}, ta[2][2] = {};
    #pragma unroll
    for (int mt = 0; mt < 2; mt++)
        #pragma unroll
        for (int dt = 0; dt < 8; dt++)
            #pragma unroll
            for (int j = 0; j < 4; j++) O[mt][dt][j] = 0.0f;

    for (int c = 0; c < 32; c++) {
        const int buf = c & 1;
        if (c == 31) asm volatile("cp.async.wait_group 0;");
        else         asm volatile("cp.async.wait_group 1;");
        __syncthreads();

        if (c == 0) {   // Q fragments (one-time)
            #pragma unroll
            for (int mt = 0; mt < 2; mt++) {
                int r0 = w * 32 + mt * 16 + qr;
                #pragma unroll
                for (int ks = 0; ks < 5; ks++) {
                    int cb = ks * 16 + qc2;
                    qf[mt][ks][0] = *(const uint32_t*)&Qs[r0 * QSTR + cb];
                    qf[mt][ks][1] = *(const uint32_t*)&Qs[(r0 + 8) * QSTR + cb];
                    qf[mt][ks][2] = *(const uint32_t*)&Qs[r0 * QSTR + cb + 8];
                    qf[mt][ks][3] = *(const uint32_t*)&Qs[(r0 + 8) * QSTR + cb + 8];
                }
            }
        }

        const __half* Kc = Ks + buf * 5632;
        const __half* Vc = Vs + buf * 4608;
        const float*  vc = vts + buf * 64;

        #pragma unroll
        for (int hh = 0; hh < 2; hh++) {      // two 32-key halves
            float sf[2][4][4];
            #pragma unroll
            for (int mt = 0; mt < 2; mt++)
                #pragma unroll
                for (int nt = 0; nt < 4; nt++)
                    #pragma unroll
                    for (int j = 0; j < 4; j++) sf[mt][nt][j] = 0.0f;

            #pragma unroll
            for (int ks = 0; ks < 5; ks++) {
                #pragma unroll
                for (int nt = 0; nt < 4; nt++) {
                    int key = hh * 32 + nt * 8 + qr;
                    uint32_t b0 = *(const uint32_t*)&Kc[key * QSTR + ks * 16 + qc2];
                    uint32_t b1 = *(const uint32_t*)&Kc[key * QSTR + ks * 16 + qc2 + 8];
                    mma16816(sf[0][nt], qf[0][ks], b0, b1);
                    mma16816(sf[1][nt], qf[1][ks], b0, b1);
                }
            }

            // softmax with fixed max 0: p = 2^s
            uint32_t ph[2][4][2];
            #pragma unroll
            for (int nt = 0; nt < 4; nt++) {
                float2 vt2 = *(const float2*)&vc[hh * 32 + nt * 8 + qc2];
                #pragma unroll
                for (int mt = 0; mt < 2; mt++) {
                    float p0 = fexp2(sf[mt][nt][0]), p1 = fexp2(sf[mt][nt][1]);
                    float p2 = fexp2(sf[mt][nt][2]), p3 = fexp2(sf[mt][nt][3]);
                    lp[mt][0] += p0 + p1;  lp[mt][1] += p2 + p3;
                    ta[mt][0] = fmaf(p0, vt2.x, fmaf(p1, vt2.y, ta[mt][0]));
                    ta[mt][1] = fmaf(p2, vt2.x, fmaf(p3, vt2.y, ta[mt][1]));
                    ph[mt][nt][0] = packh2(p0, p1);
                    ph[mt][nt][1] = packh2(p2, p3);
                }
            }

            // O += P @ V
            #pragma unroll
            for (int kt = 0; kt < 2; kt++) {
                uint32_t a0[4] = { ph[0][2*kt][0], ph[0][2*kt][1], ph[0][2*kt+1][0], ph[0][2*kt+1][1] };
                uint32_t a1[4] = { ph[1][2*kt][0], ph[1][2*kt][1], ph[1][2*kt+1][0], ph[1][2*kt+1][1] };
                int kc = hh * 32 + kt * 16 + qc2;
                #pragma unroll
                for (int dt = 0; dt < 8; dt++) {
                    int vrow = dt * 8 + qr;
                    uint32_t b0 = *(const uint32_t*)&Vc[vrow * VSTR + kc];
                    uint32_t b1 = *(const uint32_t*)&Vc[vrow * VSTR + kc + 8];
                    mma16816(O[0][dt], a0, b0, b1);
                    mma16816(O[1][dt], a1, b0, b1);
                }
            }
        }

        __syncthreads();
        if (c + 2 < 32) {
            int k0 = (c + 2) * 64;
            for (int i = tid; i < 640; i += 128) {
                int key = i / 10, sg = i % 10;
                cpa16(ksb[buf] + (key * QSTR + sg * 8) * 2, gK + (k0 + key) * DF + sg * 8);
            }
            for (int i = tid; i < 512; i += 128) {
                int d = i >> 3, sg = i & 7;
                cpa16(vsb[buf] + (d * VSTR + sg * 8) * 2, gV + (size_t)d * N_TOK + k0 + sg * 8);
            }
            if (tid < 16) cpa16(vtb[buf] + tid * 16, gvt + k0 + tid * 4);
            CP_COMMIT();
        } else {
            CP_COMMIT();   // keep group accounting uniform
        }
    }

    // epilogue: normalize + per-head Lorentz midpoint
    #pragma unroll
    for (int mt = 0; mt < 2; mt++) {
        float l0 = lp[mt][0], l1 = lp[mt][1], t0 = ta[mt][0], t1 = ta[mt][1];
        l0 += __shfl_xor_sync(0xffffffffu, l0, 1); l0 += __shfl_xor_sync(0xffffffffu, l0, 2);
        l1 += __shfl_xor_sync(0xffffffffu, l1, 1); l1 += __shfl_xor_sync(0xffffffffu, l1, 2);
        t0 += __shfl_xor_sync(0xffffffffu, t0, 1); t0 += __shfl_xor_sync(0xffffffffu, t0, 2);
        t1 += __shfl_xor_sync(0xffffffffu, t1, 1); t1 += __shfl_xor_sync(0xffffffffu, t1, 2);
        float inv0 = 1.0f / l0, inv1 = 1.0f / l1;
        float ss0 = 0.0f, ss1 = 0.0f;
        #pragma unroll
        for (int dt = 0; dt < 8; dt++) {
            O[mt][dt][0] *= inv0; O[mt][dt][1] *= inv0;
            O[mt][dt][2] *= inv1; O[mt][dt][3] *= inv1;
            ss0 += O[mt][dt][0] * O[mt][dt][0] + O[mt][dt][1] * O[mt][dt][1];
            ss1 += O[mt][dt][2] * O[mt][dt][2] + O[mt][dt][3] * O[mt][dt][3];
        }
        ss0 += __shfl_xor_sync(0xffffffffu, ss0, 1); ss0 += __shfl_xor_sync(0xffffffffu, ss0, 2);
        ss1 += __shfl_xor_sync(0xffffffffu, ss1, 1); ss1 += __shfl_xor_sync(0xffffffffu, ss1, 2);
        float mut0 = t0 * inv0, mut1 = t1 * inv1;
        float rn0 = rsqrtf(fmaxf(mut0 * mut0 - ss0, 1e-7f));
        float rn1 = rsqrtf(fmaxf(mut1 * mut1 - ss1, 1e-7f));
        int r = qt * 128 + w * 32 + mt * 16 + qr;
        size_t b0 = (size_t)(bh * N_TOK + r) * VST;
        size_t b1 = (size_t)(bh * N_TOK + r + 8) * VST;
        #pragma unroll
        for (int dt = 0; dt < 8; dt++) {
            *(float2*)&g_Mid[b0 + dt * 8 + qc2] = make_float2(O[mt][dt][0] * rn0, O[mt][dt][1] * rn0);
            *(float2*)&g_Mid[b1 + dt * 8 + qc2] = make_float2(O[mt][dt][2] * rn1, O[mt][dt][3] * rn1);
        }
        if ((lane & 3) == 0) {
            g_Mid[b0 + 64] = mut0 * rn0;
            g_Mid[b1 + 64] = mut1 * rn1;
        }
    }
}

// ---------------------------------------------------------------------------
// Finalize: mean over heads, Lorentz normalize, re-lift. One warp per (b,n).
// ---------------------------------------------------------------------------
__global__ __launch_bounds__(256) void fin_kernel(float* __restrict__ out)
{
    int warp = threadIdx.x >> 5, lane = threadIdx.x & 31;
    int row = blockIdx.x * 8 + warp;
    int b = row >> 11, n = row & (N_TOK - 1);

    float sa = 0.0f, sb2 = 0.0f, st = 0.0f;
    #pragma unroll
    for (int h = 0; h < NH; h++) {
        const float* p = &g_Mid[(size_t)((b * NH + h) * N_TOK + n) * VST];
        sa += p[lane];
        sb2 += p[32 + lane];
        if (lane == 0) st += p[64];
    }
    sa *= 0.125f; sb2 *= 0.125f; st *= 0.125f;

    float part = -(sa * sa + sb2 * sb2);
    if (lane == 0) part += st * st;
    #pragma unroll
    for (int o = 1; o < 32; o <<= 1) part += __shfl_xor_sync(0xffffffffu, part, o);
    float rn = rsqrtf(fmaxf(part, 1e-7f));

    float oa = sa * rn, ob = sb2 * rn;
    float sp = oa * oa + ob * ob;
    #pragma unroll
    for (int o = 1; o < 32; o <<= 1) sp += __shfl_xor_sync(0xffffffffu, sp, o);

    float* op = out + (size_t)row * 65;
    op[1 + lane]  = oa;
    op[33 + lane] = ob;
    if (lane == 0) op[0] = sqrtf(1.0f + sp);
}

// ---------------------------------------------------------------------------
extern "C" void kernel_launch(void* const* d_in, const int* in_sizes, int n_in,
                              void* d_out, int out_size)
{
    const float* x     = (const float*)d_in[0];
    const float* Wq    = (const float*)d_in[1];
    const float* Wk    = (const float*)d_in[2];
    const float* Wv    = (const float*)d_in[3];
    const float* bq    = (const float*)d_in[4];
    const float* bk    = (const float*)d_in[5];
    const float* bv    = (const float*)d_in[6];
    const float* scale = (const float*)d_in[7];
    (void)in_sizes; (void)n_in;

    const int smem_proj = (64 * D_INP + D_INP * 64) * 4;
    cudaFuncSetAttribute(proj_kernel, cudaFuncAttributeMaxDynamicSharedMemorySize, smem_proj);
    cudaFuncSetAttribute(attn_kernel, cudaFuncAttributeMaxDynamicSharedMemorySize, SMEM_ATTN);

    proj_kernel<<<dim3(BATCH * N_TOK / 64, NH, 3), 256, smem_proj>>>(x, Wq, Wk, Wv, bq, bk, bv, scale);
    attn_kernel<<<dim3(N_TOK / 128, BHN), 128, SMEM_ATTN>>>();
    fin_kernel<<<(BATCH * N_TOK) / 8, 256>>>((float*)d_out);
}

// round 5
// speedup vs baseline: 8.2954x; 1.5961x over previous
#include <cuda_runtime.h>
#include <cuda_fp16.h>
#include <math.h>
#include <stdint.h>

constexpr int BATCH = 4, N_TOK = 2048, D_INP = 129, NH = 8, BHN = 32, VST = 68;
constexpr int DF = 80;      // padded feature dim for Q/K (64 spatial + 3 extras + 13 zero)

// Scratch (BSS zero-init; Q/K pad columns 67-79 never written -> stay zero)
__device__ __align__(128) __half g_Qh[BHN * N_TOK * DF];
__device__ __align__(128) __half g_Kh[BHN * N_TOK * DF];
__device__ __align__(128) __half g_Vh[BHN * 64 * N_TOK];   // d-major: [bh][d][n]
__device__ __align__(128) float  g_Vt [BHN * N_TOK];
__device__ __align__(128) float  g_Mid[BHN * N_TOK * VST];
// proj staging
__device__ __align__(128) __half g_Xh [8192 * 136];        // fp16 x, cols 129..135 = 0
__device__ __align__(128) __half g_Whn[1536 * 136];        // fp16 W, n-major rows, cols 129..135 = 0
__device__ __align__(128) float  g_bias[1536];
__device__ __align__(128) float  g_w128[1536];             // W row k=128 (time), fp32

__device__ __forceinline__ float fexp2(float x) {
    float r; asm("ex2.approx.ftz.f32 %0, %1;" : "=f"(r) : "f"(x)); return r;
}
__device__ __forceinline__ uint32_t smem_u32(const void* p) {
    uint32_t a;
    asm("{ .reg .u64 t; cvta.to.shared.u64 t, %1; cvt.u32.u64 %0, t; }" : "=r"(a) : "l"(p));
    return a;
}
__device__ __forceinline__ void cpa16(uint32_t d, const void* s) {
    asm volatile("cp.async.cg.shared.global [%0], [%1], 16;" :: "r"(d), "l"(s));
}
#define CP_COMMIT() asm volatile("cp.async.commit_group;")
__device__ __forceinline__ void mma16816(float* c, const uint32_t* a, uint32_t b0, uint32_t b1) {
    asm volatile("mma.sync.aligned.m16n8k16.row.col.f32.f16.f16.f32 "
                 "{%0,%1,%2,%3},{%4,%5,%6,%7},{%8,%9},{%0,%1,%2,%3};"
                 : "+f"(c[0]), "+f"(c[1]), "+f"(c[2]), "+f"(c[3])
                 : "r"(a[0]), "r"(a[1]), "r"(a[2]), "r"(a[3]), "r"(b0), "r"(b1));
}
__device__ __forceinline__ uint32_t packh2(float lo, float hi) {
    __half2 h = __floats2half2_rn(lo, hi);
    return *(uint32_t*)&h;
}

// ---------------------------------------------------------------------------
// cvt: build fp16 GEMM operands + fp32 bias/w128 tables.
// ---------------------------------------------------------------------------
__global__ __launch_bounds__(256) void cvt_kernel(
    const float* __restrict__ x,
    const float* __restrict__ Wq, const float* __restrict__ Wk, const float* __restrict__ Wv,
    const float* __restrict__ bq, const float* __restrict__ bk, const float* __restrict__ bv)
{
    int i = blockIdx.x * 256 + threadIdx.x;
    const int NX = 8192 * 136, NW = 1536 * 136;
    if (i < NX) {
        int r = i / 136, k = i - r * 136;
        g_Xh[i] = __float2half_rn(k < 129 ? x[r * 129 + k] : 0.0f);
    } else if (i < NX + NW) {
        int j2 = i - NX;
        int j = j2 / 136, k = j2 - j * 136;
        int z = j >> 9, h = (j >> 6) & 7, d = j & 63;
        const float* W = (z == 0) ? Wq : (z == 1 ? Wk : Wv);
        g_Whn[j2] = __float2half_rn(k < 129 ? W[(h * 129 + k) * 64 + d] : 0.0f);
    } else if (i < NX + NW + 1536) {
        int j = i - NX - NW;
        int z = j >> 9, h = (j >> 6) & 7, d = j & 63;
        const float* W = (z == 0) ? Wq : (z == 1 ? Wk : Wv);
        const float* bb = (z == 0) ? bq : (z == 1 ? bk : bv);
        g_bias[j] = bb[h * 64 + d];
        g_w128[j] = W[(h * 129 + 128) * 64 + d];
    }
}

// ---------------------------------------------------------------------------
// Tensor-core projection: C[128x128] = Xh[128x128k] @ Whn^T, fp32 rank-1 fix
// for input dim 128 + bias, fused lift + alpha-fold + layout writes.
// grid (64 m-tiles, 12 n-tiles), 128 threads.
// ---------------------------------------------------------------------------
constexpr int PST = 136;                      // smem row stride (halves)
constexpr int SMEM_PROJ = 2 * 128 * PST * 2;  // 69632 B

__global__ __launch_bounds__(128) void projmma_kernel(
    const float* __restrict__ x, const float* __restrict__ scale)
{
    extern __shared__ __align__(16) __half pshm[];
    __half* Xs = pshm;               // [128][136]
    __half* Wsm = pshm + 128 * PST;  // [128][136]
    const uint32_t smb = smem_u32(pshm);
    const uint32_t smw = smb + 128 * PST * 2;

    const int tid = threadIdx.x;
    const int w = tid >> 5, lane = tid & 31;
    const int qr = lane >> 2, qc2 = (lane & 3) * 2;
    const int m0 = blockIdx.x * 128, n0 = blockIdx.y * 128;
    const int z = n0 >> 9, h0 = (n0 >> 6) & 7;

    const __half* gX = g_Xh + (size_t)m0 * 136;
    const __half* gW = g_Whn + (size_t)n0 * 136;
    for (int i = tid; i < 2176; i += 128) {
        int r = i / 17, c = i - r * 17;
        cpa16(smb + r * (PST * 2) + c * 16, gX + r * 136 + c * 8);
        cpa16(smw + r * (PST * 2) + c * 16, gW + r * 136 + c * 8);
    }
    CP_COMMIT();
    asm volatile("cp.async.wait_group 0;");
    __syncthreads();

    float c[2][16][4];
    #pragma unroll
    for (int mt = 0; mt < 2; mt++)
        #pragma unroll
        for (int nt = 0; nt < 16; nt++)
            #pragma unroll
            for (int j = 0; j < 4; j++) c[mt][nt][j] = 0.0f;

    #pragma unroll
    for (int ks = 0; ks < 8; ks++) {
        uint32_t a[2][4];
        #pragma unroll
        for (int mt = 0; mt < 2; mt++) {
            int r0 = w * 32 + mt * 16 + qr;
            int cb = ks * 16 + qc2;
            a[mt][0] = *(const uint32_t*)&Xs[r0 * PST + cb];
            a[mt][1] = *(const uint32_t*)&Xs[(r0 + 8) * PST + cb];
            a[mt][2] = *(const uint32_t*)&Xs[r0 * PST + cb + 8];
            a[mt][3] = *(const uint32_t*)&Xs[(r0 + 8) * PST + cb + 8];
        }
        #pragma unroll
        for (int nt = 0; nt < 16; nt++) {
            uint32_t b0 = *(const uint32_t*)&Wsm[(nt * 8 + qr) * PST + ks * 16 + qc2];
            uint32_t b1 = *(const uint32_t*)&Wsm[(nt * 8 + qr) * PST + ks * 16 + qc2 + 8];
            mma16816(c[0][nt], a[0], b0, b1);
            mma16816(c[1][nt], a[1], b0, b1);
        }
    }

    float fac = 1.0f;
    if (z == 0) { float sc = *scale; fac = 2.0f * 1.4426950408889634f / (sc + 1e-7f); }

    #pragma unroll
    for (int mt = 0; mt < 2; mt++) {
        int r0 = w * 32 + mt * 16 + qr;
        int mA = m0 + r0, mB = mA + 8;
        float xta = x[(size_t)mA * 129 + 128];
        float xtb = x[(size_t)mB * 129 + 128];

        float ssA[2] = {0.0f, 0.0f}, ssB[2] = {0.0f, 0.0f};
        #pragma unroll
        for (int nt = 0; nt < 16; nt++) {
            int col = n0 + nt * 8 + qc2;
            float2 bi = *(const float2*)&g_bias[col];
            float2 wc = *(const float2*)&g_w128[col];
            float s0 = c[mt][nt][0] + xta * wc.x + bi.x;
            float s1 = c[mt][nt][1] + xta * wc.y + bi.y;
            float s2 = c[mt][nt][2] + xtb * wc.x + bi.x;
            float s3 = c[mt][nt][3] + xtb * wc.y + bi.y;
            c[mt][nt][0] = s0; c[mt][nt][1] = s1; c[mt][nt][2] = s2; c[mt][nt][3] = s3;
            int g = nt >> 3;
            ssA[g] += s0 * s0 + s1 * s1;
            ssB[g] += s2 * s2 + s3 * s3;
        }
        #pragma unroll
        for (int g = 0; g < 2; g++) {
            ssA[g] += __shfl_xor_sync(0xffffffffu, ssA[g], 1);
            ssA[g] += __shfl_xor_sync(0xffffffffu, ssA[g], 2);
            ssB[g] += __shfl_xor_sync(0xffffffffu, ssB[g], 1);
            ssB[g] += __shfl_xor_sync(0xffffffffu, ssB[g], 2);
        }

        int b = mA >> 11, nA = mA & 2047, nB = mB & 2047;
        #pragma unroll
        for (int g = 0; g < 2; g++) {
            float tA = sqrtf(1.0f + ssA[g]), apA = ssA[g] / (1.0f + tA);
            float tB = sqrtf(1.0f + ssB[g]), apB = ssB[g] / (1.0f + tB);
            int bh = b * NH + h0 + g;
            if (z < 2) {
                __half* gq = (z == 0) ? g_Qh : g_Kh;
                size_t baseA = (size_t)(bh * N_TOK + nA) * DF;
                size_t baseB = (size_t)(bh * N_TOK + nB) * DF;
                #pragma unroll
                for (int nt = g * 8; nt < g * 8 + 8; nt++) {
                    int d0 = (nt & 7) * 8 + qc2;
                    *(__half2*)&gq[baseA + d0] = __floats2half2_rn(fac * c[mt][nt][0], fac * c[mt][nt][1]);
                    *(__half2*)&gq[baseB + d0] = __floats2half2_rn(fac * c[mt][nt][2], fac * c[mt][nt][3]);
                }
                if (qc2 == 0) {
                    float a64, a65, a66, b64, b65, b66;
                    if (z == 0) {
                        a64 = -fac * apA; a65 = -fac; a66 = -fac * apA;
                        b64 = -fac * apB; b65 = -fac; b66 = -fac * apB;
                    } else {
                        a64 = 1.0f; a65 = apA; a66 = apA;
                        b64 = 1.0f; b65 = apB; b66 = apB;
                    }
                    *(__half2*)&gq[baseA + 64] = __floats2half2_rn(a64, a65);
                    *(__half2*)&gq[baseA + 66] = __floats2half2_rn(a66, 0.0f);
                    *(__half2*)&gq[baseB + 64] = __floats2half2_rn(b64, b65);
                    *(__half2*)&gq[baseB + 66] = __floats2half2_rn(b66, 0.0f);
                }
            } else {
                #pragma unroll
                for (int nt = g * 8; nt < g * 8 + 8; nt++) {
                    int d0 = (nt & 7) * 8 + qc2;
                    g_Vh[(size_t)(bh * 64 + d0)     * N_TOK + nA] = __float2half_rn(c[mt][nt][0]);
                    g_Vh[(size_t)(bh * 64 + d0 + 1) * N_TOK + nA] = __float2half_rn(c[mt][nt][1]);
                    g_Vh[(size_t)(bh * 64 + d0)     * N_TOK + nB] = __float2half_rn(c[mt][nt][2]);
                    g_Vh[(size_t)(bh * 64 + d0 + 1) * N_TOK + nB] = __float2half_rn(c[mt][nt][3]);
                }
                if (qc2 == 0) {
                    g_Vt[bh * N_TOK + nA] = tA;
                    g_Vt[bh * N_TOK + nB] = tB;
                }
            }
        }
    }
}

// ---------------------------------------------------------------------------
// FA2-style fp16 flash attention, fixed-max-0 softmax (unchanged from R4).
// ---------------------------------------------------------------------------
constexpr int QSTR = 88, VSTR = 72;
constexpr int SMEM_ATTN = 64000;

__global__ __launch_bounds__(128, 1) void attn_kernel()
{
    extern __shared__ __align__(16) __half smh[];
    __half* Qs = smh;
    __half* Ks = smh + 11264;
    __half* Vs = smh + 22528;
    float*  vts = (float*)(smh + 31744);

    const uint32_t smb = smem_u32(smh);
    const int tid = threadIdx.x;
    const int w = tid >> 5, lane = tid & 31;
    const int qr = lane >> 2, qc2 = (lane & 3) * 2;
    const int bh = blockIdx.y, qt = blockIdx.x;

    const __half* gQ = g_Qh + (size_t)bh * N_TOK * DF + (size_t)qt * 128 * DF;
    const __half* gK = g_Kh + (size_t)bh * N_TOK * DF;
    const __half* gV = g_Vh + (size_t)bh * 64 * N_TOK;
    const float*  gvt = g_Vt + bh * N_TOK;

    const uint32_t ksb[2] = { smb + 11264u * 2, smb + 16896u * 2 };
    const uint32_t vsb[2] = { smb + 22528u * 2, smb + 27136u * 2 };
    const uint32_t vtb[2] = { smb + 31744u * 2, smb + 31744u * 2 + 256 };

    for (int i = tid; i < 1280; i += 128) {
        int r = i / 10, sg = i % 10;
        cpa16(smb + (r * QSTR + sg * 8) * 2, gQ + r * DF + sg * 8);
    }
    #pragma unroll 1
    for (int c = 0; c < 2; c++) {
        int k0 = c * 64;
        for (int i = tid; i < 640; i += 128) {
            int key = i / 10, sg = i % 10;
            cpa16(ksb[c] + (key * QSTR + sg * 8) * 2, gK + (k0 + key) * DF + sg * 8);
        }
        for (int i = tid; i < 512; i += 128) {
            int d = i >> 3, sg = i & 7;
            cpa16(vsb[c] + (d * VSTR + sg * 8) * 2, gV + (size_t)d * N_TOK + k0 + sg * 8);
        }
        if (tid < 16) cpa16(vtb[c] + tid * 16, gvt + k0 + tid * 4);
        CP_COMMIT();
    }

    uint32_t qf[2][5][4];
    float O[2][8][4];
    float lp[2][2] = {}, ta[2][2] = {};
    #pragma unroll
    for (int mt = 0; mt < 2; mt++)
        #pragma unroll
        for (int dt = 0; dt < 8; dt++)
            #pragma unroll
            for (int j = 0; j < 4; j++) O[mt][dt][j] = 0.0f;

    for (int c = 0; c < 32; c++) {
        const int buf = c & 1;
        if (c == 31) asm volatile("cp.async.wait_group 0;");
        else         asm volatile("cp.async.wait_group 1;");
        __syncthreads();

        if (c == 0) {
            #pragma unroll
            for (int mt = 0; mt < 2; mt++) {
                int r0 = w * 32 + mt * 16 + qr;
                #pragma unroll
                for (int ks = 0; ks < 5; ks++) {
                    int cb = ks * 16 + qc2;
                    qf[mt][ks][0] = *(const uint32_t*)&Qs[r0 * QSTR + cb];
                    qf[mt][ks][1] = *(const uint32_t*)&Qs[(r0 + 8) * QSTR + cb];
                    qf[mt][ks][2] = *(const uint32_t*)&Qs[r0 * QSTR + cb + 8];
                    qf[mt][ks][3] = *(const uint32_t*)&Qs[(r0 + 8) * QSTR + cb + 8];
                }
            }
        }

        const __half* Kc = Ks + buf * 5632;
        const __half* Vc = Vs + buf * 4608;
        const float*  vc = vts + buf * 64;

        #pragma unroll
        for (int hh = 0; hh < 2; hh++) {
            float sf[2][4][4];
            #pragma unroll
            for (int mt = 0; mt < 2; mt++)
                #pragma unroll
                for (int nt = 0; nt < 4; nt++)
                    #pragma unroll
                    for (int j = 0; j < 4; j++) sf[mt][nt][j] = 0.0f;

            #pragma unroll
            for (int ks = 0; ks < 5; ks++) {
                #pragma unroll
                for (int nt = 0; nt < 4; nt++) {
                    int key = hh * 32 + nt * 8 + qr;
                    uint32_t b0 = *(const uint32_t*)&Kc[key * QSTR + ks * 16 + qc2];
                    uint32_t b1 = *(const uint32_t*)&Kc[key * QSTR + ks * 16 + qc2 + 8];
                    mma16816(sf[0][nt], qf[0][ks], b0, b1);
                    mma16816(sf[1][nt], qf[1][ks], b0, b1);
                }
            }

            uint32_t ph[2][4][2];
            #pragma unroll
            for (int nt = 0; nt < 4; nt++) {
                float2 vt2 = *(const float2*)&vc[hh * 32 + nt * 8 + qc2];
                #pragma unroll
                for (int mt = 0; mt < 2; mt++) {
                    float p0 = fexp2(sf[mt][nt][0]), p1 = fexp2(sf[mt][nt][1]);
                    float p2 = fexp2(sf[mt][nt][2]), p3 = fexp2(sf[mt][nt][3]);
                    lp[mt][0] += p0 + p1;  lp[mt][1] += p2 + p3;
                    ta[mt][0] = fmaf(p0, vt2.x, fmaf(p1, vt2.y, ta[mt][0]));
                    ta[mt][1] = fmaf(p2, vt2.x, fmaf(p3, vt2.y, ta[mt][1]));
                    ph[mt][nt][0] = packh2(p0, p1);
                    ph[mt][nt][1] = packh2(p2, p3);
                }
            }

            #pragma unroll
            for (int kt = 0; kt < 2; kt++) {
                uint32_t a0[4] = { ph[0][2*kt][0], ph[0][2*kt][1], ph[0][2*kt+1][0], ph[0][2*kt+1][1] };
                uint32_t a1[4] = { ph[1][2*kt][0], ph[1][2*kt][1], ph[1][2*kt+1][0], ph[1][2*kt+1][1] };
                int kc = hh * 32 + kt * 16 + qc2;
                #pragma unroll
                for (int dt = 0; dt < 8; dt++) {
                    int vrow = dt * 8 + qr;
                    uint32_t b0 = *(const uint32_t*)&Vc[vrow * VSTR + kc];
                    uint32_t b1 = *(const uint32_t*)&Vc[vrow * VSTR + kc + 8];
                    mma16816(O[0][dt], a0, b0, b1);
                    mma16816(O[1][dt], a1, b0, b1);
                }
            }
        }

        __syncthreads();
        if (c + 2 < 32) {
            int k0 = (c + 2) * 64;
            for (int i = tid; i < 640; i += 128) {
                int key = i / 10, sg = i % 10;
                cpa16(ksb[buf] + (key * QSTR + sg * 8) * 2, gK + (k0 + key) * DF + sg * 8);
            }
            for (int i = tid; i < 512; i += 128) {
                int d = i >> 3, sg = i & 7;
                cpa16(vsb[buf] + (d * VSTR + sg * 8) * 2, gV + (size_t)d * N_TOK + k0 + sg * 8);
            }
            if (tid < 16) cpa16(vtb[buf] + tid * 16, gvt + k0 + tid * 4);
            CP_COMMIT();
        } else {
            CP_COMMIT();
        }
    }

    #pragma unroll
    for (int mt = 0; mt < 2; mt++) {
        float l0 = lp[mt][0], l1 = lp[mt][1], t0 = ta[mt][0], t1 = ta[mt][1];
        l0 += __shfl_xor_sync(0xffffffffu, l0, 1); l0 += __shfl_xor_sync(0xffffffffu, l0, 2);
        l1 += __shfl_xor_sync(0xffffffffu, l1, 1); l1 += __shfl_xor_sync(0xffffffffu, l1, 2);
        t0 += __shfl_xor_sync(0xffffffffu, t0, 1); t0 += __shfl_xor_sync(0xffffffffu, t0, 2);
        t1 += __shfl_xor_sync(0xffffffffu, t1, 1); t1 += __shfl_xor_sync(0xffffffffu, t1, 2);
        float inv0 = 1.0f / l0, inv1 = 1.0f / l1;
        float ss0 = 0.0f, ss1 = 0.0f;
        #pragma unroll
        for (int dt = 0; dt < 8; dt++) {
            O[mt][dt][0] *= inv0; O[mt][dt][1] *= inv0;
            O[mt][dt][2] *= inv1; O[mt][dt][3] *= inv1;
            ss0 += O[mt][dt][0] * O[mt][dt][0] + O[mt][dt][1] * O[mt][dt][1];
            ss1 += O[mt][dt][2] * O[mt][dt][2] + O[mt][dt][3] * O[mt][dt][3];
        }
        ss0 += __shfl_xor_sync(0xffffffffu, ss0, 1); ss0 += __shfl_xor_sync(0xffffffffu, ss0, 2);
        ss1 += __shfl_xor_sync(0xffffffffu, ss1, 1); ss1 += __shfl_xor_sync(0xffffffffu, ss1, 2);
        float mut0 = t0 * inv0, mut1 = t1 * inv1;
        float rn0 = rsqrtf(fmaxf(mut0 * mut0 - ss0, 1e-7f));
        float rn1 = rsqrtf(fmaxf(mut1 * mut1 - ss1, 1e-7f));
        int r = qt * 128 + w * 32 + mt * 16 + qr;
        size_t b0 = (size_t)(bh * N_TOK + r) * VST;
        size_t b1 = (size_t)(bh * N_TOK + r + 8) * VST;
        #pragma unroll
        for (int dt = 0; dt < 8; dt++) {
            *(float2*)&g_Mid[b0 + dt * 8 + qc2] = make_float2(O[mt][dt][0] * rn0, O[mt][dt][1] * rn0);
            *(float2*)&g_Mid[b1 + dt * 8 + qc2] = make_float2(O[mt][dt][2] * rn1, O[mt][dt][3] * rn1);
        }
        if ((lane & 3) == 0) {
            g_Mid[b0 + 64] = mut0 * rn0;
            g_Mid[b1 + 64] = mut1 * rn1;
        }
    }
}

// ---------------------------------------------------------------------------
__global__ __launch_bounds__(256) void fin_kernel(float* __restrict__ out)
{
    int warp = threadIdx.x >> 5, lane = threadIdx.x & 31;
    int row = blockIdx.x * 8 + warp;
    int b = row >> 11, n = row & (N_TOK - 1);

    float sa = 0.0f, sb2 = 0.0f, st = 0.0f;
    #pragma unroll
    for (int h = 0; h < NH; h++) {
        const float* p = &g_Mid[(size_t)((b * NH + h) * N_TOK + n) * VST];
        sa += p[lane];
        sb2 += p[32 + lane];
        if (lane == 0) st += p[64];
    }
    sa *= 0.125f; sb2 *= 0.125f; st *= 0.125f;

    float part = -(sa * sa + sb2 * sb2);
    if (lane == 0) part += st * st;
    #pragma unroll
    for (int o = 1; o < 32; o <<= 1) part += __shfl_xor_sync(0xffffffffu, part, o);
    float rn = rsqrtf(fmaxf(part, 1e-7f));

    float oa = sa * rn, ob = sb2 * rn;
    float sp = oa * oa + ob * ob;
    #pragma unroll
    for (int o = 1; o < 32; o <<= 1) sp += __shfl_xor_sync(0xffffffffu, sp, o);

    float* op = out + (size_t)row * 65;
    op[1 + lane]  = oa;
    op[33 + lane] = ob;
    if (lane == 0) op[0] = sqrtf(1.0f + sp);
}

// ---------------------------------------------------------------------------
extern "C" void kernel_launch(void* const* d_in, const int* in_sizes, int n_in,
                              void* d_out, int out_size)
{
    const float* x     = (const float*)d_in[0];
    const float* Wq    = (const float*)d_in[1];
    const float* Wk    = (const float*)d_in[2];
    const float* Wv    = (const float*)d_in[3];
    const float* bq    = (const float*)d_in[4];
    const float* bk    = (const float*)d_in[5];
    const float* bv    = (const float*)d_in[6];
    const float* scale = (const float*)d_in[7];
    (void)in_sizes; (void)n_in;

    cudaFuncSetAttribute(projmma_kernel, cudaFuncAttributeMaxDynamicSharedMemorySize, SMEM_PROJ);
    cudaFuncSetAttribute(attn_kernel, cudaFuncAttributeMaxDynamicSharedMemorySize, SMEM_ATTN);

    const int total = 8192 * 136 + 1536 * 136 + 1536;
    cvt_kernel<<<(total + 255) / 256, 256>>>(x, Wq, Wk, Wv, bq, bk, bv);
    projmma_kernel<<<dim3(64, 12), 128, SMEM_PROJ>>>(x, scale);
    attn_kernel<<<dim3(N_TOK / 128, BHN), 128, SMEM_ATTN>>>();
    fin_kernel<<<(BATCH * N_TOK) / 8, 256>>>((float*)d_out);
}